// round 8
// baseline (speedup 1.0000x reference)
#include <cuda_runtime.h>
#include <math_constants.h>

// Coords padded to float4 -> single LDG.128 per gather (16B aligned by definition).
__device__ float4 g_coords4[131072];

__global__ void __launch_bounds__(256) pad_coords_kernel(
    const float* __restrict__ coords, int n)
{
    int i = blockIdx.x * blockDim.x + threadIdx.x;
    if (i < n) {
        g_coords4[i] = make_float4(coords[3 * i + 0],
                                   coords[3 * i + 1],
                                   coords[3 * i + 2], 0.0f);
    }
    __threadfence();
    cudaTriggerProgrammaticLaunchCompletion();
}

#define EPB 512   // edges per chunk (2 per thread, 256 threads)

// Output layout (float32, out_size = 6*E):
//   [0 , 3E) : vec [E,3]   [3E,4E) : dist   [4E,5E) : switch   [5E,6E) : mask
__global__ void __launch_bounds__(256) graph_edge_kernel(
    const int*   __restrict__ esrc,
    const int*   __restrict__ edst,
    const float* __restrict__ shifts,
    const float* __restrict__ cells,
    float*       __restrict__ out,
    int E)
{
    __shared__ float s_cells[9];
    __shared__ float stage[EPB * 3];

    const int t = threadIdx.x;
    if (t < 9) s_cells[t] = __ldg(cells + t);

    const int nchunks = (E + EPB - 1) / EPB;
    const int stride  = gridDim.x;

    int chunk = blockIdx.x;

    // ---- prologue: issue streaming loads for first chunk ----
    int cs0i = 0, cd0i = 0, cs1i = 0, cd1i = 0;
    float csx0 = 0.f, csy0 = 0.f, csz0 = 0.f, csx1 = 0.f, csy1 = 0.f, csz1 = 0.f;
    if (chunk < nchunks) {
        const int i0 = chunk * EPB + t;
        const int i1 = i0 + 256;
        if (i0 < E) {
            cs0i = __ldg(esrc + i0);
            cd0i = __ldg(edst + i0);
            csx0 = __ldg(shifts + 3 * i0 + 0);
            csy0 = __ldg(shifts + 3 * i0 + 1);
            csz0 = __ldg(shifts + 3 * i0 + 2);
        }
        if (i1 < E) {
            cs1i = __ldg(esrc + i1);
            cd1i = __ldg(edst + i1);
            csx1 = __ldg(shifts + 3 * i1 + 0);
            csy1 = __ldg(shifts + 3 * i1 + 1);
            csz1 = __ldg(shifts + 3 * i1 + 2);
        }
    }

    // PDL: wait for pad_coords_kernel before any gather.
    cudaGridDependencySynchronize();
    __syncthreads();   // s_cells visibility (hidden under in-flight loads)

    while (chunk < nchunks) {
        const int base = chunk * EPB;
        const int i0 = base + t;
        const int i1 = i0 + 256;
        const bool a0 = (i0 < E);
        const bool a1 = (i1 < E);

        // ---- prefetch next chunk's streaming data (hides idx DRAM latency) ----
        const int next = chunk + stride;
        int ns0i = 0, nd0i = 0, ns1i = 0, nd1i = 0;
        float nsx0 = 0.f, nsy0 = 0.f, nsz0 = 0.f, nsx1 = 0.f, nsy1 = 0.f, nsz1 = 0.f;
        if (next < nchunks) {
            const int j0 = next * EPB + t;
            const int j1 = j0 + 256;
            if (j0 < E) {
                ns0i = __ldg(esrc + j0);
                nd0i = __ldg(edst + j0);
                nsx0 = __ldg(shifts + 3 * j0 + 0);
                nsy0 = __ldg(shifts + 3 * j0 + 1);
                nsz0 = __ldg(shifts + 3 * j0 + 2);
            }
            if (j1 < E) {
                ns1i = __ldg(esrc + j1);
                nd1i = __ldg(edst + j1);
                nsx1 = __ldg(shifts + 3 * j1 + 0);
                nsy1 = __ldg(shifts + 3 * j1 + 1);
                nsz1 = __ldg(shifts + 3 * j1 + 2);
            }
        }

        // ---- gathers for current chunk (idx arrived during previous iteration) ----
        float4 g_s0 = make_float4(0.f,0.f,0.f,0.f), g_d0 = g_s0, g_s1 = g_s0, g_d1 = g_s0;
        if (a0) { g_d0 = g_coords4[cd0i]; g_s0 = g_coords4[cs0i]; }
        if (a1) { g_d1 = g_coords4[cd1i]; g_s1 = g_coords4[cs1i]; }

        float dist0 = 0.f, sw0 = 0.f, mf0 = 0.f;
        float dist1 = 0.f, sw1 = 0.f, mf1 = 0.f;

        if (a0) {
            const float vx = (g_d0.x - g_s0.x) + csx0 * s_cells[0] + csy0 * s_cells[3] + csz0 * s_cells[6];
            const float vy = (g_d0.y - g_s0.y) + csx0 * s_cells[1] + csy0 * s_cells[4] + csz0 * s_cells[7];
            const float vz = (g_d0.z - g_s0.z) + csx0 * s_cells[2] + csy0 * s_cells[5] + csz0 * s_cells[8];
            stage[3 * t + 0] = vx;
            stage[3 * t + 1] = vy;
            stage[3 * t + 2] = vz;
            dist0 = sqrtf(vx * vx + vy * vy + vz * vz);
            const bool m = dist0 < 5.0f;
            sw0 = m ? (0.5f * __cosf(dist0 * (CUDART_PI_F / 5.0f)) + 0.5f) : 0.0f;
            mf0 = m ? 1.0f : 0.0f;
        }
        if (a1) {
            const int u = t + 256;
            const float vx = (g_d1.x - g_s1.x) + csx1 * s_cells[0] + csy1 * s_cells[3] + csz1 * s_cells[6];
            const float vy = (g_d1.y - g_s1.y) + csx1 * s_cells[1] + csy1 * s_cells[4] + csz1 * s_cells[7];
            const float vz = (g_d1.z - g_s1.z) + csx1 * s_cells[2] + csy1 * s_cells[5] + csz1 * s_cells[8];
            stage[3 * u + 0] = vx;
            stage[3 * u + 1] = vy;
            stage[3 * u + 2] = vz;
            dist1 = sqrtf(vx * vx + vy * vy + vz * vz);
            const bool m = dist1 < 5.0f;
            sw1 = m ? (0.5f * __cosf(dist1 * (CUDART_PI_F / 5.0f)) + 0.5f) : 0.0f;
            mf1 = m ? 1.0f : 0.0f;
        }

        __syncthreads();   // stage writes visible

        const int nf = min(EPB, E - base) * 3;
        #pragma unroll
        for (int k = t; k < EPB * 3; k += 256) {
            if (k < nf) out[base * 3 + k] = stage[k];
        }

        if (a0) {
            out[3 * E + i0] = dist0;
            out[4 * E + i0] = sw0;
            out[5 * E + i0] = mf0;
        }
        if (a1) {
            out[3 * E + i1] = dist1;
            out[4 * E + i1] = sw1;
            out[5 * E + i1] = mf1;
        }

        __syncthreads();   // stage reads done before next iteration overwrites

        // ---- rotate pipeline registers ----
        cs0i = ns0i; cd0i = nd0i; cs1i = ns1i; cd1i = nd1i;
        csx0 = nsx0; csy0 = nsy0; csz0 = nsz0;
        csx1 = nsx1; csy1 = nsy1; csz1 = nsz1;
        chunk = next;
    }
}

extern "C" void kernel_launch(void* const* d_in, const int* in_sizes, int n_in,
                              void* d_out, int out_size)
{
    const float* coords = (const float*)d_in[0];
    const int*   esrc   = (const int*)  d_in[1];
    const int*   edst   = (const int*)  d_in[2];
    const float* shifts = (const float*)d_in[3];
    const float* cells  = (const float*)d_in[4];
    float*       out    = (float*)d_out;

    const int N = in_sizes[0] / 3;
    const int E = in_sizes[1];
    const int nchunks = (E + EPB - 1) / EPB;

    pad_coords_kernel<<<(N + 255) / 256, 256>>>(coords, N);

    // Size grid to exactly fill the chip (persistent blocks, one wave).
    int blocks = 888;  // fallback: 148 SMs * 6
    {
        int dev = 0, sms = 0, maxb = 0;
        if (cudaGetDevice(&dev) == cudaSuccess &&
            cudaDeviceGetAttribute(&sms, cudaDevAttrMultiProcessorCount, dev) == cudaSuccess &&
            cudaOccupancyMaxActiveBlocksPerMultiprocessor(&maxb, graph_edge_kernel, 256, 0) == cudaSuccess &&
            sms > 0 && maxb > 0) {
            blocks = sms * maxb;
        }
    }
    if (blocks > nchunks) blocks = nchunks;

    // PDL launch; fall back to a plain launch on error.
    cudaLaunchConfig_t cfg = {};
    cfg.gridDim  = dim3(blocks, 1, 1);
    cfg.blockDim = dim3(256, 1, 1);
    cfg.dynamicSmemBytes = 0;
    cfg.stream = 0;
    cudaLaunchAttribute attr[1];
    attr[0].id = cudaLaunchAttributeProgrammaticStreamSerialization;
    attr[0].val.programmaticStreamSerializationAllowed = 1;
    cfg.attrs = attr;
    cfg.numAttrs = 1;

    cudaError_t err = cudaLaunchKernelEx(&cfg, graph_edge_kernel,
                                         esrc, edst, shifts, cells, out, E);
    if (err != cudaSuccess) {
        (void)cudaGetLastError();
        graph_edge_kernel<<<blocks, 256>>>(esrc, edst, shifts, cells, out, E);
    }
}